// round 9
// baseline (speedup 1.0000x reference)
#include <cuda_runtime.h>
#include <cuda_bf16.h>
#include <cstdint>
#include <cfloat>
#include <math.h>

// Problem constants
#define MB   256
#define NP   16384
#define KD   2048
#define PPOS 4
#define KSEL 54
#define INV_TEMP 20.0f

// GEMM tiling: BM=128, BN=128, BK=32. 4 warps (2m x 2n), warp tile 64x64.
// 2 CTAs per SM for cross-CTA latency/sync overlap.
#define BN 128
#define BK 32
#define NTHR 128
#define GNIT (KD / BK)          // 64
#define A_STAGE 8192            // 128 rows * 64 B (bf16)
#define B_STAGE 8192            // 128 rows * 64 B (bf16)

// Scratch
__device__ __nv_bfloat16 g_Abf[(size_t)MB * KD];
__device__ float g_score[(size_t)MB * NP];

// ---------------------------------------------------------------------------
__device__ __forceinline__ uint32_t smem_u32(const void* p) {
    uint32_t a;
    asm("{ .reg .u64 t; cvta.to.shared.u64 t, %1; cvt.u32.u64 %0, t; }"
        : "=r"(a) : "l"(p));
    return a;
}
__device__ __forceinline__ void cp16(uint32_t sa, const void* g) {
    asm volatile("cp.async.cg.shared.global [%0], [%1], 16;\n" :: "r"(sa), "l"(g));
}
__device__ __forceinline__ void cp_commit() { asm volatile("cp.async.commit_group;\n"); }
__device__ __forceinline__ void cp_wait0()  { asm volatile("cp.async.wait_group 0;\n"); }

__device__ __forceinline__ void mma_bf16(float c[4],
                                         uint32_t a0, uint32_t a1, uint32_t a2, uint32_t a3,
                                         uint32_t b0, uint32_t b1) {
    asm volatile(
        "mma.sync.aligned.m16n8k16.row.col.f32.bf16.bf16.f32 "
        "{%0,%1,%2,%3}, {%4,%5,%6,%7}, {%8,%9}, {%0,%1,%2,%3};\n"
        : "+f"(c[0]), "+f"(c[1]), "+f"(c[2]), "+f"(c[3])
        : "r"(a0), "r"(a1), "r"(a2), "r"(a3), "r"(b0), "r"(b1));
}
__device__ __forceinline__ void ldsm4(uint32_t& r0, uint32_t& r1, uint32_t& r2,
                                      uint32_t& r3, uint32_t addr) {
    asm volatile("ldmatrix.sync.aligned.m8n8.x4.shared.b16 {%0,%1,%2,%3}, [%4];"
                 : "=r"(r0), "=r"(r1), "=r"(r2), "=r"(r3) : "r"(addr));
}
__device__ __forceinline__ uint32_t pk(float x, float y) {
    __nv_bfloat162 h = __floats2bfloat162_rn(x, y);
    return *(uint32_t*)&h;
}
__device__ __forceinline__ uint32_t f2key(float v) {
    uint32_t f = __float_as_uint(v);
    return (f & 0x80000000u) ? ~f : (f | 0x80000000u);
}
__device__ __forceinline__ float key2f(uint32_t u) {
    uint32_t f = (u & 0x80000000u) ? (u ^ 0x80000000u) : ~u;
    return __uint_as_float(f);
}
// SW64 swizzle for 64-byte rows
#define SWZ64(o) ((o) ^ ((((uint32_t)(o)) >> 3) & 0x30))

// ---------------------------------------------------------------------------
// Kernel 0: convert A to bf16 once; thread 0 zeroes the output scalar.
// ---------------------------------------------------------------------------
__global__ void convertA_kernel(const float* __restrict__ A, float* __restrict__ out) {
    int i = blockIdx.x * blockDim.x + threadIdx.x;
    float4 v = ((const float4*)A)[i];
    ((uint2*)g_Abf)[i] = make_uint2(pk(v.x, v.y), pk(v.z, v.w));
    if (i == 0) out[0] = 0.0f;
}

// ---------------------------------------------------------------------------
// Kernel 1: C[256,16384] = A @ B^T, bf16 mma.sync + ldmatrix.
// Grid (2,128) m-fastest; 128 threads = 4 warps (2m x 2n), warp tile 64x64.
// Same two-sync schedule as R5; 2 CTAs/SM.
// ---------------------------------------------------------------------------
extern __shared__ char smem_g[];

__global__ __launch_bounds__(NTHR, 2) void gemm_bf16_kernel(const float* __restrict__ B) {
    const uint32_t sbase = smem_u32(smem_g);
    const uint32_t Asu = sbase;                     // 2 stages A
    const uint32_t Bsu = sbase + 2 * A_STAGE;       // 2 stages B
    char* Bsg = smem_g + 2 * A_STAGE;

    const int tid  = threadIdx.x;
    const int lane = tid & 31;
    const int warp = tid >> 5;
    const int wm = (warp >> 1) * 64;
    const int wn = (warp & 1) * 64;
    const int gM = blockIdx.x * 128;
    const int gN = blockIdx.y * BN;

    // ldmatrix lane roles
    const int rowin = lane & 7;
    const int ph    = lane >> 3;                    // 0..3
    const int mArow = (ph & 1) * 8 + rowin;
    const int kAoff = (ph >> 1) * 16;
    const int nBrow = (ph >> 1) * 8 + rowin;
    const int kBoff = (ph & 1) * 16;

    float acc[4][8][4];
#pragma unroll
    for (int i = 0; i < 4; ++i)
#pragma unroll
        for (int j = 0; j < 8; ++j)
#pragma unroll
            for (int q = 0; q < 4; ++q) acc[i][j][q] = 0.0f;

    const __nv_bfloat16* Ag = g_Abf + (size_t)gM * KD;
    const float* Bg = B + (size_t)gN * KD;

    // B register prefetch: 4 bf16-output 16B-segments per thread (2 float4 each)
    float4 br0[4], br1[4];
#pragma unroll
    for (int j = 0; j < 4; ++j) {
        int id = tid + NTHR * j, r = id >> 2, sg = id & 3;
        const float* s = Bg + (size_t)r * KD + sg * 8;
        br0[j] = *(const float4*)s;
        br1[j] = *(const float4*)(s + 4);
    }
    // A tile 0 via cp.async (4 chunks/thread)
#pragma unroll
    for (int j = 0; j < 4; ++j) {
        int id = tid + NTHR * j, r = id >> 2, c = id & 3;
        cp16(Asu + SWZ64(r * 64 + c * 16), Ag + (size_t)r * KD + c * 8);
    }
    cp_commit();

    for (int it = 0; it < GNIT; ++it) {
        const int st = it & 1;
        cp_wait0();
        __syncthreads();

        // STS B_it (convert prefetched fp32 -> bf16, SW64 swizzled)
#pragma unroll
        for (int j = 0; j < 4; ++j) {
            int id = tid + NTHR * j, r = id >> 2, sg = id & 3;
            uint4 v = make_uint4(pk(br0[j].x, br0[j].y), pk(br0[j].z, br0[j].w),
                                 pk(br1[j].x, br1[j].y), pk(br1[j].z, br1[j].w));
            *(uint4*)(Bsg + st * B_STAGE + SWZ64(r * 64 + sg * 16)) = v;
        }

        if (it + 1 < GNIT) {
            const int ko = (it + 1) * BK;
            // prefetch next B
#pragma unroll
            for (int j = 0; j < 4; ++j) {
                int id = tid + NTHR * j, r = id >> 2, sg = id & 3;
                const float* s = Bg + (size_t)r * KD + ko + sg * 8;
                br0[j] = *(const float4*)s;
                br1[j] = *(const float4*)(s + 4);
            }
            // cp.async next A
            const uint32_t an = Asu + (st ^ 1) * A_STAGE;
#pragma unroll
            for (int j = 0; j < 4; ++j) {
                int id = tid + NTHR * j, r = id >> 2, c = id & 3;
                cp16(an + SWZ64(r * 64 + c * 16), Ag + (size_t)r * KD + ko + c * 8);
            }
            cp_commit();
        }
        __syncthreads();

        const uint32_t ab = Asu + st * A_STAGE;
        const uint32_t bb = Bsu + st * B_STAGE;
#pragma unroll
        for (int s = 0; s < 2; ++s) {
            const int kb = s * 32;
            uint32_t a[4][4];
#pragma unroll
            for (int mt = 0; mt < 4; ++mt) {
                int m = wm + mt * 16 + mArow;
                ldsm4(a[mt][0], a[mt][1], a[mt][2], a[mt][3],
                      ab + SWZ64(m * 64 + kb + kAoff));
            }
            uint32_t b[8][2];
#pragma unroll
            for (int np = 0; np < 4; ++np) {
                int n = wn + np * 16 + nBrow;
                ldsm4(b[np * 2][0], b[np * 2][1], b[np * 2 + 1][0], b[np * 2 + 1][1],
                      bb + SWZ64(n * 64 + kb + kBoff));
            }
#pragma unroll
            for (int mt = 0; mt < 4; ++mt)
#pragma unroll
                for (int nt = 0; nt < 8; ++nt)
                    mma_bf16(acc[mt][nt], a[mt][0], a[mt][1], a[mt][2], a[mt][3],
                             b[nt][0], b[nt][1]);
        }
    }

    // epilogue
    const int gr = lane >> 2;
    const int cB = gN + wn + (lane & 3) * 2;
#pragma unroll
    for (int mt = 0; mt < 4; ++mt) {
#pragma unroll
        for (int nt = 0; nt < 8; ++nt) {
            int rr = gM + wm + mt * 16 + gr;
            int cc = cB + nt * 8;
            *(float2*)&g_score[(size_t)rr * NP + cc] =
                make_float2(acc[mt][nt][0], acc[mt][nt][1]);
            *(float2*)&g_score[(size_t)(rr + 8) * NP + cc] =
                make_float2(acc[mt][nt][2], acc[mt][nt][3]);
        }
    }
}

// ---------------------------------------------------------------------------
// Kernel 2: per-row exact radix-select top-K + log-softmax loss + fused mean.
// (R5-proven version, 256 threads.)
// ---------------------------------------------------------------------------
__global__ void topk_loss_kernel(const int* __restrict__ targets,
                                 const int* __restrict__ apl,
                                 const int* __restrict__ plt,
                                 float* __restrict__ out) {
    extern __shared__ uint32_t skey[];   // 16384 keys
    __shared__ uint32_t hist[256];
    __shared__ uint32_t sfx[256];
    __shared__ float    redf[256];
    __shared__ int      redi[256];
    __shared__ uint32_t s_prefix;
    __shared__ int      s_want;
    __shared__ int      posIdx[PPOS];
    __shared__ float    posVal[PPOS];
    __shared__ int      nd_s;
    __shared__ uint32_t s_maxkey;
    __shared__ float    s_m;
    __shared__ float    s_f4x;
    __shared__ int      s_exIdx;

    const int r = blockIdx.x;
    const int tid = threadIdx.x;
    const float4* row4 = (const float4*)(g_score + (size_t)r * NP);

#pragma unroll 4
    for (int j = 0; j < NP / 4 / 256; ++j) {
        int i = tid + 256 * j;
        float4 v = row4[i];
        skey[i * 4 + 0] = f2key(v.x * INV_TEMP);
        skey[i * 4 + 1] = f2key(v.y * INV_TEMP);
        skey[i * 4 + 2] = f2key(v.z * INV_TEMP);
        skey[i * 4 + 3] = f2key(v.w * INV_TEMP);
    }
    if (tid == 0) { s_maxkey = 0; s_f4x = 0.0f; }
    __syncthreads();

    if (tid == 0) {
        int t = targets[r];
        int y = apl[t];
        int nd = 0;
        for (int j = 0; j < PPOS; ++j) {
            int p = plt[y * PPOS + j];
            bool dup = false;
            for (int q = 0; q < j; ++q)
                if (plt[y * PPOS + q] == p) dup = true;
            if (!dup) { posIdx[nd] = p; posVal[nd] = key2f(skey[p]); ++nd; }
        }
        for (int q = 0; q < nd; ++q) skey[posIdx[q]] = 0u;
        nd_s = nd;
    }
    __syncthreads();
    const int nd  = nd_s;
    const int nbg = KSEL - nd;

    uint32_t prefix = 0;
    int want = nbg;
#pragma unroll
    for (int p = 3; p >= 0; --p) {
        hist[tid] = 0;
        __syncthreads();
        uint32_t lmax = 0;
#pragma unroll 8
        for (int j = 0; j < NP / 256; ++j) {
            uint32_t u = skey[tid + 256 * j];
            if (p == 3) {
                lmax = max(lmax, u);
                atomicAdd(&hist[u >> 24], 1u);
            } else if ((u >> ((p + 1) * 8)) == prefix) {
                atomicAdd(&hist[(u >> (p * 8)) & 0xFFu], 1u);
            }
        }
        if (p == 3) atomicMax(&s_maxkey, lmax);
        __syncthreads();

        uint32_t h = hist[tid];
        sfx[tid] = h;
        __syncthreads();
#pragma unroll
        for (int o = 1; o < 256; o <<= 1) {
            uint32_t v = sfx[tid];
            if (tid + o < 256) v += sfx[tid + o];
            __syncthreads();
            sfx[tid] = v;
            __syncthreads();
        }
        uint32_t excl = sfx[tid] - h;
        if ((int)excl < want && (int)(excl + h) >= want) {
            s_prefix = (prefix << 8) | (uint32_t)tid;
            s_want = want - (int)excl;
        }
        __syncthreads();
        prefix = s_prefix;
        want = s_want;
        __syncthreads();
    }
    const uint32_t T = prefix;
    const int wantEq = want;

    if (tid == 0) {
        float m = key2f(s_maxkey);
        for (int q = 0; q < nd; ++q) m = fmaxf(m, posVal[q]);
        s_m = m;
    }
    __syncthreads();
    const float m = s_m;

    float se = 0.0f;
#pragma unroll 8
    for (int j = 0; j < NP / 256; ++j) {
        uint32_t u = skey[tid + 256 * j];
        if (u > T) se += expf(key2f(u) - m);
    }
    redf[tid] = se;
    __syncthreads();
#pragma unroll
    for (int o = 128; o > 0; o >>= 1) {
        if (tid < o) redf[tid] += redf[tid + o];
        __syncthreads();
    }

    // rare: nd < 4 -> top (4-nd) background values complete the first-P sum
    for (int e = 0; e < PPOS - nd; ++e) {
        uint32_t bk = 0; int bi = -1;
#pragma unroll 8
        for (int j = 0; j < NP / 256; ++j) {
            int i = tid + 256 * j;
            uint32_t u = skey[i];
            if (u > bk) { bk = u; bi = i; }
        }
        sfx[tid] = bk; redi[tid] = bi;
        __syncthreads();
#pragma unroll
        for (int o = 128; o > 0; o >>= 1) {
            if (tid < o && sfx[tid + o] > sfx[tid]) {
                sfx[tid] = sfx[tid + o]; redi[tid] = redi[tid + o];
            }
            __syncthreads();
        }
        if (tid == 0) { s_f4x += key2f(sfx[0]); s_exIdx = redi[0]; }
        __syncthreads();
        if ((s_exIdx & 255) == tid) skey[s_exIdx] = 0u;
        __syncthreads();
    }

    if (tid == 0) {
        float seTot = redf[0] + (float)wantEq * expf(key2f(T) - m);
        float f4 = s_f4x;
        for (int q = 0; q < nd; ++q) {
            seTot += expf(posVal[q] - m);
            f4 += posVal[q];
        }
        float lse = m + logf(seTot);
        atomicAdd(out, (lse - 0.25f * f4) * (1.0f / MB));
    }
}

// ---------------------------------------------------------------------------
extern "C" void kernel_launch(void* const* d_in, const int* in_sizes, int n_in,
                              void* d_out, int out_size) {
    const float* features = (const float*)d_in[0];
    const float* em       = (const float*)d_in[1];
    const int*   targets  = (const int*)d_in[2];
    const int*   apl      = (const int*)d_in[3];
    const int*   plt      = (const int*)d_in[4];
    float* out = (float*)d_out;

    const int gemm_smem = 2 * (A_STAGE + B_STAGE);   // 32768
    cudaFuncSetAttribute(gemm_bf16_kernel,
                         cudaFuncAttributeMaxDynamicSharedMemorySize, gemm_smem);
    const int topk_smem = NP * sizeof(uint32_t);     // 65536
    cudaFuncSetAttribute(topk_loss_kernel,
                         cudaFuncAttributeMaxDynamicSharedMemorySize, topk_smem);

    convertA_kernel<<<(MB * KD / 4) / 128, 128>>>(features, out);
    dim3 grid(2, NP / BN);   // m fastest -> B shared via L2
    gemm_bf16_kernel<<<grid, NTHR, gemm_smem>>>(em);
    topk_loss_kernel<<<MB, 256, topk_smem>>>(targets, apl, plt, out);
}

// round 10
// speedup vs baseline: 1.2136x; 1.2136x over previous
#include <cuda_runtime.h>
#include <cuda_bf16.h>
#include <cstdint>
#include <cfloat>
#include <math.h>

// Problem constants
#define MB   256
#define NP   16384
#define KD   2048
#define PPOS 4
#define KSEL 54
#define INV_TEMP 20.0f

// GEMM tiling: BM=256 (all of M), BN=128, BK=64. 8 warps (4m x 2n), warp 64x64.
#define BN 128
#define BK 64
#define NTHR 256
#define GNIT (KD / BK)          // 32
#define A_STAGE 32768           // 256 rows * 128 B
#define B_STAGE 16384           // 128 rows * 128 B

// Scratch
__device__ __nv_bfloat16 g_Abf[(size_t)MB * KD];
__device__ float g_score[(size_t)MB * NP];

// ---------------------------------------------------------------------------
__device__ __forceinline__ uint32_t smem_u32(const void* p) {
    uint32_t a;
    asm("{ .reg .u64 t; cvta.to.shared.u64 t, %1; cvt.u32.u64 %0, t; }"
        : "=r"(a) : "l"(p));
    return a;
}
__device__ __forceinline__ void cp16(uint32_t sa, const void* g) {
    asm volatile("cp.async.cg.shared.global [%0], [%1], 16;\n" :: "r"(sa), "l"(g));
}
__device__ __forceinline__ void cp_commit() { asm volatile("cp.async.commit_group;\n"); }
__device__ __forceinline__ void cp_wait0()  { asm volatile("cp.async.wait_group 0;\n"); }

__device__ __forceinline__ void mma_bf16(float c[4],
                                         uint32_t a0, uint32_t a1, uint32_t a2, uint32_t a3,
                                         uint32_t b0, uint32_t b1) {
    asm volatile(
        "mma.sync.aligned.m16n8k16.row.col.f32.bf16.bf16.f32 "
        "{%0,%1,%2,%3}, {%4,%5,%6,%7}, {%8,%9}, {%0,%1,%2,%3};\n"
        : "+f"(c[0]), "+f"(c[1]), "+f"(c[2]), "+f"(c[3])
        : "r"(a0), "r"(a1), "r"(a2), "r"(a3), "r"(b0), "r"(b1));
}
__device__ __forceinline__ void ldsm4(uint32_t& r0, uint32_t& r1, uint32_t& r2,
                                      uint32_t& r3, uint32_t addr) {
    asm volatile("ldmatrix.sync.aligned.m8n8.x4.shared.b16 {%0,%1,%2,%3}, [%4];"
                 : "=r"(r0), "=r"(r1), "=r"(r2), "=r"(r3) : "r"(addr));
}
__device__ __forceinline__ uint32_t pk(float x, float y) {
    __nv_bfloat162 h = __floats2bfloat162_rn(x, y);
    return *(uint32_t*)&h;
}
__device__ __forceinline__ uint32_t f2key(float v) {
    uint32_t f = __float_as_uint(v);
    return (f & 0x80000000u) ? ~f : (f | 0x80000000u);
}
__device__ __forceinline__ float key2f(uint32_t u) {
    uint32_t f = (u & 0x80000000u) ? (u ^ 0x80000000u) : ~u;
    return __uint_as_float(f);
}
#define SWZ(o) ((o) ^ ((((uint32_t)(o)) >> 3) & 0x70))

// ---------------------------------------------------------------------------
// Kernel 0: convert A to bf16 once; thread 0 zeroes the output scalar.
// ---------------------------------------------------------------------------
__global__ void convertA_kernel(const float* __restrict__ A, float* __restrict__ out) {
    int i = blockIdx.x * blockDim.x + threadIdx.x;
    float4 v = ((const float4*)A)[i];
    ((uint2*)g_Abf)[i] = make_uint2(pk(v.x, v.y), pk(v.z, v.w));
    if (i == 0) out[0] = 0.0f;
}

// ---------------------------------------------------------------------------
// Kernel 1: C[256,16384] = A @ B^T, bf16 mma.sync + ldmatrix.
// Grid 128 (n-tiles), 256 threads = 8 warps (4m x 2n), warp tile 64x64.
// R5 structure; compute loop software-pipelined (double-buffered fragments).
// ---------------------------------------------------------------------------
extern __shared__ char smem_g[];

__global__ __launch_bounds__(NTHR, 1) void gemm_bf16_kernel(const float* __restrict__ B) {
    const uint32_t sbase = smem_u32(smem_g);
    const uint32_t Asu = sbase;                     // 2 stages A
    const uint32_t Bsu = sbase + 2 * A_STAGE;       // 2 stages B
    char* Bsg = smem_g + 2 * A_STAGE;

    const int tid  = threadIdx.x;
    const int lane = tid & 31;
    const int warp = tid >> 5;
    const int wm = (warp >> 1) * 64;
    const int wn = (warp & 1) * 64;
    const int gN = blockIdx.x * BN;

    // ldmatrix lane roles
    const int rowin = lane & 7;
    const int ph    = lane >> 3;                    // 0..3
    const int mArow = (ph & 1) * 8 + rowin;
    const int kAoff = (ph >> 1) * 16;
    const int nBrow = (ph >> 1) * 8 + rowin;
    const int kBoff = (ph & 1) * 16;

    float acc[4][8][4];
#pragma unroll
    for (int i = 0; i < 4; ++i)
#pragma unroll
        for (int j = 0; j < 8; ++j)
#pragma unroll
            for (int q = 0; q < 4; ++q) acc[i][j][q] = 0.0f;

    const float* Bg = B + (size_t)gN * KD;

    // B register prefetch: 4 output 16B-segments per thread (2 float4 each)
    float4 br0[4], br1[4];
#pragma unroll
    for (int j = 0; j < 4; ++j) {
        int id = tid + 256 * j, r = id >> 3, sg = id & 7;
        const float* s = Bg + (size_t)r * KD + sg * 8;
        br0[j] = *(const float4*)s;
        br1[j] = *(const float4*)(s + 4);
    }
    // A tile 0 via cp.async (8 chunks/thread)
#pragma unroll
    for (int j = 0; j < 8; ++j) {
        int id = tid + 256 * j, r = id >> 3, c = id & 7;
        cp16(Asu + SWZ(r * 128 + c * 16), g_Abf + (size_t)r * KD + c * 8);
    }
    cp_commit();

    for (int it = 0; it < GNIT; ++it) {
        const int st = it & 1;
        cp_wait0();
        __syncthreads();

        // STS B_it (convert prefetched fp32 -> bf16, swizzled)
#pragma unroll
        for (int j = 0; j < 4; ++j) {
            int id = tid + 256 * j, r = id >> 3, sg = id & 7;
            uint4 v = make_uint4(pk(br0[j].x, br0[j].y), pk(br0[j].z, br0[j].w),
                                 pk(br1[j].x, br1[j].y), pk(br1[j].z, br1[j].w));
            *(uint4*)(Bsg + st * B_STAGE + SWZ(r * 128 + sg * 16)) = v;
        }

        if (it + 1 < GNIT) {
            const int ko = (it + 1) * BK;
            // prefetch next B
#pragma unroll
            for (int j = 0; j < 4; ++j) {
                int id = tid + 256 * j, r = id >> 3, sg = id & 7;
                const float* s = Bg + (size_t)r * KD + ko + sg * 8;
                br0[j] = *(const float4*)s;
                br1[j] = *(const float4*)(s + 4);
            }
            // cp.async next A
            const uint32_t an = Asu + (st ^ 1) * A_STAGE;
#pragma unroll
            for (int j = 0; j < 8; ++j) {
                int id = tid + 256 * j, r = id >> 3, c = id & 7;
                cp16(an + SWZ(r * 128 + c * 16), g_Abf + (size_t)r * KD + ko + c * 8);
            }
            cp_commit();
        }
        __syncthreads();

        const uint32_t ab = Asu + st * A_STAGE;
        const uint32_t bb = Bsu + st * B_STAGE;

        // software-pipelined s-loop: double-buffered fragments
        uint32_t a2[2][4][4];
        uint32_t b2[2][8][2];

        // preload s = 0
#pragma unroll
        for (int mt = 0; mt < 4; ++mt) {
            int m = wm + mt * 16 + mArow;
            ldsm4(a2[0][mt][0], a2[0][mt][1], a2[0][mt][2], a2[0][mt][3],
                  ab + SWZ(m * 128 + kAoff));
        }
#pragma unroll
        for (int np = 0; np < 4; ++np) {
            int n = wn + np * 16 + nBrow;
            ldsm4(b2[0][np * 2][0], b2[0][np * 2][1],
                  b2[0][np * 2 + 1][0], b2[0][np * 2 + 1][1],
                  bb + SWZ(n * 128 + kBoff));
        }

#pragma unroll
        for (int s = 0; s < 4; ++s) {
            const int cur = s & 1;
            const int nxt = cur ^ 1;
            if (s < 3) {
                const int kb = (s + 1) * 32;
#pragma unroll
                for (int mt = 0; mt < 4; ++mt) {
                    int m = wm + mt * 16 + mArow;
                    ldsm4(a2[nxt][mt][0], a2[nxt][mt][1], a2[nxt][mt][2], a2[nxt][mt][3],
                          ab + SWZ(m * 128 + kb + kAoff));
                }
#pragma unroll
                for (int np = 0; np < 4; ++np) {
                    int n = wn + np * 16 + nBrow;
                    ldsm4(b2[nxt][np * 2][0], b2[nxt][np * 2][1],
                          b2[nxt][np * 2 + 1][0], b2[nxt][np * 2 + 1][1],
                          bb + SWZ(n * 128 + kb + kBoff));
                }
            }
#pragma unroll
            for (int mt = 0; mt < 4; ++mt)
#pragma unroll
                for (int nt = 0; nt < 8; ++nt)
                    mma_bf16(acc[mt][nt],
                             a2[cur][mt][0], a2[cur][mt][1], a2[cur][mt][2], a2[cur][mt][3],
                             b2[cur][nt][0], b2[cur][nt][1]);
        }
    }

    // epilogue
    const int gr = lane >> 2;
    const int cB = gN + wn + (lane & 3) * 2;
#pragma unroll
    for (int mt = 0; mt < 4; ++mt) {
#pragma unroll
        for (int nt = 0; nt < 8; ++nt) {
            int rr = wm + mt * 16 + gr;
            int cc = cB + nt * 8;
            *(float2*)&g_score[(size_t)rr * NP + cc] =
                make_float2(acc[mt][nt][0], acc[mt][nt][1]);
            *(float2*)&g_score[(size_t)(rr + 8) * NP + cc] =
                make_float2(acc[mt][nt][2], acc[mt][nt][3]);
        }
    }
}

// ---------------------------------------------------------------------------
// Kernel 2: per-row exact radix-select top-K + log-softmax loss + fused mean.
// (R5-proven version, 256 threads.)
// ---------------------------------------------------------------------------
__global__ void topk_loss_kernel(const int* __restrict__ targets,
                                 const int* __restrict__ apl,
                                 const int* __restrict__ plt,
                                 float* __restrict__ out) {
    extern __shared__ uint32_t skey[];   // 16384 keys
    __shared__ uint32_t hist[256];
    __shared__ uint32_t sfx[256];
    __shared__ float    redf[256];
    __shared__ int      redi[256];
    __shared__ uint32_t s_prefix;
    __shared__ int      s_want;
    __shared__ int      posIdx[PPOS];
    __shared__ float    posVal[PPOS];
    __shared__ int      nd_s;
    __shared__ uint32_t s_maxkey;
    __shared__ float    s_m;
    __shared__ float    s_f4x;
    __shared__ int      s_exIdx;

    const int r = blockIdx.x;
    const int tid = threadIdx.x;
    const float4* row4 = (const float4*)(g_score + (size_t)r * NP);

#pragma unroll 4
    for (int j = 0; j < NP / 4 / 256; ++j) {
        int i = tid + 256 * j;
        float4 v = row4[i];
        skey[i * 4 + 0] = f2key(v.x * INV_TEMP);
        skey[i * 4 + 1] = f2key(v.y * INV_TEMP);
        skey[i * 4 + 2] = f2key(v.z * INV_TEMP);
        skey[i * 4 + 3] = f2key(v.w * INV_TEMP);
    }
    if (tid == 0) { s_maxkey = 0; s_f4x = 0.0f; }
    __syncthreads();

    if (tid == 0) {
        int t = targets[r];
        int y = apl[t];
        int nd = 0;
        for (int j = 0; j < PPOS; ++j) {
            int p = plt[y * PPOS + j];
            bool dup = false;
            for (int q = 0; q < j; ++q)
                if (plt[y * PPOS + q] == p) dup = true;
            if (!dup) { posIdx[nd] = p; posVal[nd] = key2f(skey[p]); ++nd; }
        }
        for (int q = 0; q < nd; ++q) skey[posIdx[q]] = 0u;
        nd_s = nd;
    }
    __syncthreads();
    const int nd  = nd_s;
    const int nbg = KSEL - nd;

    uint32_t prefix = 0;
    int want = nbg;
#pragma unroll
    for (int p = 3; p >= 0; --p) {
        hist[tid] = 0;
        __syncthreads();
        uint32_t lmax = 0;
#pragma unroll 8
        for (int j = 0; j < NP / 256; ++j) {
            uint32_t u = skey[tid + 256 * j];
            if (p == 3) {
                lmax = max(lmax, u);
                atomicAdd(&hist[u >> 24], 1u);
            } else if ((u >> ((p + 1) * 8)) == prefix) {
                atomicAdd(&hist[(u >> (p * 8)) & 0xFFu], 1u);
            }
        }
        if (p == 3) atomicMax(&s_maxkey, lmax);
        __syncthreads();

        uint32_t h = hist[tid];
        sfx[tid] = h;
        __syncthreads();
#pragma unroll
        for (int o = 1; o < 256; o <<= 1) {
            uint32_t v = sfx[tid];
            if (tid + o < 256) v += sfx[tid + o];
            __syncthreads();
            sfx[tid] = v;
            __syncthreads();
        }
        uint32_t excl = sfx[tid] - h;
        if ((int)excl < want && (int)(excl + h) >= want) {
            s_prefix = (prefix << 8) | (uint32_t)tid;
            s_want = want - (int)excl;
        }
        __syncthreads();
        prefix = s_prefix;
        want = s_want;
        __syncthreads();
    }
    const uint32_t T = prefix;
    const int wantEq = want;

    if (tid == 0) {
        float m = key2f(s_maxkey);
        for (int q = 0; q < nd; ++q) m = fmaxf(m, posVal[q]);
        s_m = m;
    }
    __syncthreads();
    const float m = s_m;

    float se = 0.0f;
#pragma unroll 8
    for (int j = 0; j < NP / 256; ++j) {
        uint32_t u = skey[tid + 256 * j];
        if (u > T) se += expf(key2f(u) - m);
    }
    redf[tid] = se;
    __syncthreads();
#pragma unroll
    for (int o = 128; o > 0; o >>= 1) {
        if (tid < o) redf[tid] += redf[tid + o];
        __syncthreads();
    }

    // rare: nd < 4 -> top (4-nd) background values complete the first-P sum
    for (int e = 0; e < PPOS - nd; ++e) {
        uint32_t bk = 0; int bi = -1;
#pragma unroll 8
        for (int j = 0; j < NP / 256; ++j) {
            int i = tid + 256 * j;
            uint32_t u = skey[i];
            if (u > bk) { bk = u; bi = i; }
        }
        sfx[tid] = bk; redi[tid] = bi;
        __syncthreads();
#pragma unroll
        for (int o = 128; o > 0; o >>= 1) {
            if (tid < o && sfx[tid + o] > sfx[tid]) {
                sfx[tid] = sfx[tid + o]; redi[tid] = redi[tid + o];
            }
            __syncthreads();
        }
        if (tid == 0) { s_f4x += key2f(sfx[0]); s_exIdx = redi[0]; }
        __syncthreads();
        if ((s_exIdx & 255) == tid) skey[s_exIdx] = 0u;
        __syncthreads();
    }

    if (tid == 0) {
        float seTot = redf[0] + (float)wantEq * expf(key2f(T) - m);
        float f4 = s_f4x;
        for (int q = 0; q < nd; ++q) {
            seTot += expf(posVal[q] - m);
            f4 += posVal[q];
        }
        float lse = m + logf(seTot);
        atomicAdd(out, (lse - 0.25f * f4) * (1.0f / MB));
    }
}

// ---------------------------------------------------------------------------
extern "C" void kernel_launch(void* const* d_in, const int* in_sizes, int n_in,
                              void* d_out, int out_size) {
    const float* features = (const float*)d_in[0];
    const float* em       = (const float*)d_in[1];
    const int*   targets  = (const int*)d_in[2];
    const int*   apl      = (const int*)d_in[3];
    const int*   plt      = (const int*)d_in[4];
    float* out = (float*)d_out;

    const int gemm_smem = 2 * (A_STAGE + B_STAGE);   // 98304
    cudaFuncSetAttribute(gemm_bf16_kernel,
                         cudaFuncAttributeMaxDynamicSharedMemorySize, gemm_smem);
    const int topk_smem = NP * sizeof(uint32_t);     // 65536
    cudaFuncSetAttribute(topk_loss_kernel,
                         cudaFuncAttributeMaxDynamicSharedMemorySize, topk_smem);

    convertA_kernel<<<(MB * KD / 4) / 128, 128>>>(features, out);
    gemm_bf16_kernel<<<NP / BN, NTHR, gemm_smem>>>(em);
    topk_loss_kernel<<<MB, 256, topk_smem>>>(targets, apl, plt, out);
}

// round 11
// speedup vs baseline: 1.2467x; 1.0273x over previous
#include <cuda_runtime.h>
#include <cuda_bf16.h>
#include <cstdint>
#include <cfloat>
#include <math.h>

// Problem constants
#define MB   256
#define NP   16384
#define KD   2048
#define PPOS 4
#define KSEL 54
#define INV_TEMP 20.0f

// GEMM tiling: BM=256 (all of M), BN=128, BK=64. 8 warps (4m x 2n), warp 64x64.
#define BN 128
#define BK 64
#define NTHR 256
#define GNIT (KD / BK)          // 32
#define A_STAGE 32768           // 256 rows * 128 B
#define B_STAGE 16384           // 128 rows * 128 B

// Scratch
__device__ __nv_bfloat16 g_Abf[(size_t)MB * KD];
__device__ float g_score[(size_t)MB * NP];

// ---------------------------------------------------------------------------
__device__ __forceinline__ uint32_t smem_u32(const void* p) {
    uint32_t a;
    asm("{ .reg .u64 t; cvta.to.shared.u64 t, %1; cvt.u32.u64 %0, t; }"
        : "=r"(a) : "l"(p));
    return a;
}
__device__ __forceinline__ void cp16(uint32_t sa, const void* g) {
    asm volatile("cp.async.cg.shared.global [%0], [%1], 16;\n" :: "r"(sa), "l"(g));
}
__device__ __forceinline__ void cp_commit() { asm volatile("cp.async.commit_group;\n"); }
__device__ __forceinline__ void cp_wait0()  { asm volatile("cp.async.wait_group 0;\n"); }

__device__ __forceinline__ void mma_bf16(float c[4],
                                         uint32_t a0, uint32_t a1, uint32_t a2, uint32_t a3,
                                         uint32_t b0, uint32_t b1) {
    asm volatile(
        "mma.sync.aligned.m16n8k16.row.col.f32.bf16.bf16.f32 "
        "{%0,%1,%2,%3}, {%4,%5,%6,%7}, {%8,%9}, {%0,%1,%2,%3};\n"
        : "+f"(c[0]), "+f"(c[1]), "+f"(c[2]), "+f"(c[3])
        : "r"(a0), "r"(a1), "r"(a2), "r"(a3), "r"(b0), "r"(b1));
}
__device__ __forceinline__ void ldsm4(uint32_t& r0, uint32_t& r1, uint32_t& r2,
                                      uint32_t& r3, uint32_t addr) {
    asm volatile("ldmatrix.sync.aligned.m8n8.x4.shared.b16 {%0,%1,%2,%3}, [%4];"
                 : "=r"(r0), "=r"(r1), "=r"(r2), "=r"(r3) : "r"(addr));
}
__device__ __forceinline__ uint32_t pk(float x, float y) {
    __nv_bfloat162 h = __floats2bfloat162_rn(x, y);
    return *(uint32_t*)&h;
}
__device__ __forceinline__ uint32_t f2key(float v) {
    uint32_t f = __float_as_uint(v);
    return (f & 0x80000000u) ? ~f : (f | 0x80000000u);
}
__device__ __forceinline__ float key2f(uint32_t u) {
    uint32_t f = (u & 0x80000000u) ? (u ^ 0x80000000u) : ~u;
    return __uint_as_float(f);
}
#define SWZ(o) ((o) ^ ((((uint32_t)(o)) >> 3) & 0x70))

// ---------------------------------------------------------------------------
// Kernel 0: convert A to bf16 once (MLP=4 per thread); zero the output scalar.
// ---------------------------------------------------------------------------
__global__ void convertA_kernel(const float* __restrict__ A, float* __restrict__ out) {
    const int base = blockIdx.x * blockDim.x + threadIdx.x;   // 32768 threads
#pragma unroll
    for (int j = 0; j < 4; ++j) {
        int i = base + 32768 * j;
        float4 v = ((const float4*)A)[i];
        ((uint2*)g_Abf)[i] = make_uint2(pk(v.x, v.y), pk(v.z, v.w));
    }
    if (base == 0) out[0] = 0.0f;
}

// ---------------------------------------------------------------------------
// Kernel 1: C[256,16384] = A @ B^T, bf16 mma.sync + ldmatrix.
// Grid 128 (n-tiles), 256 threads = 8 warps (4m x 2n), warp tile 64x64.
// (R5-proven version, byte-identical.)
// ---------------------------------------------------------------------------
extern __shared__ char smem_g[];

__global__ __launch_bounds__(NTHR, 1) void gemm_bf16_kernel(const float* __restrict__ B) {
    const uint32_t sbase = smem_u32(smem_g);
    const uint32_t Asu = sbase;                     // 2 stages A
    const uint32_t Bsu = sbase + 2 * A_STAGE;       // 2 stages B
    char* Bsg = smem_g + 2 * A_STAGE;

    const int tid  = threadIdx.x;
    const int lane = tid & 31;
    const int warp = tid >> 5;
    const int wm = (warp >> 1) * 64;
    const int wn = (warp & 1) * 64;
    const int gN = blockIdx.x * BN;

    // ldmatrix lane roles
    const int rowin = lane & 7;
    const int ph    = lane >> 3;                    // 0..3
    const int mArow = (ph & 1) * 8 + rowin;
    const int kAoff = (ph >> 1) * 16;
    const int nBrow = (ph >> 1) * 8 + rowin;
    const int kBoff = (ph & 1) * 16;

    float acc[4][8][4];
#pragma unroll
    for (int i = 0; i < 4; ++i)
#pragma unroll
        for (int j = 0; j < 8; ++j)
#pragma unroll
            for (int q = 0; q < 4; ++q) acc[i][j][q] = 0.0f;

    const float* Bg = B + (size_t)gN * KD;

    // B register prefetch: 4 output 16B-segments per thread (2 float4 each)
    float4 br0[4], br1[4];
#pragma unroll
    for (int j = 0; j < 4; ++j) {
        int id = tid + 256 * j, r = id >> 3, sg = id & 7;
        const float* s = Bg + (size_t)r * KD + sg * 8;
        br0[j] = *(const float4*)s;
        br1[j] = *(const float4*)(s + 4);
    }
    // A tile 0 via cp.async (8 chunks/thread)
#pragma unroll
    for (int j = 0; j < 8; ++j) {
        int id = tid + 256 * j, r = id >> 3, c = id & 7;
        cp16(Asu + SWZ(r * 128 + c * 16), g_Abf + (size_t)r * KD + c * 8);
    }
    cp_commit();

    for (int it = 0; it < GNIT; ++it) {
        const int st = it & 1;
        cp_wait0();
        __syncthreads();

        // STS B_it (convert prefetched fp32 -> bf16, swizzled)
#pragma unroll
        for (int j = 0; j < 4; ++j) {
            int id = tid + 256 * j, r = id >> 3, sg = id & 7;
            uint4 v = make_uint4(pk(br0[j].x, br0[j].y), pk(br0[j].z, br0[j].w),
                                 pk(br1[j].x, br1[j].y), pk(br1[j].z, br1[j].w));
            *(uint4*)(Bsg + st * B_STAGE + SWZ(r * 128 + sg * 16)) = v;
        }

        if (it + 1 < GNIT) {
            const int ko = (it + 1) * BK;
            // prefetch next B
#pragma unroll
            for (int j = 0; j < 4; ++j) {
                int id = tid + 256 * j, r = id >> 3, sg = id & 7;
                const float* s = Bg + (size_t)r * KD + ko + sg * 8;
                br0[j] = *(const float4*)s;
                br1[j] = *(const float4*)(s + 4);
            }
            // cp.async next A
            const uint32_t an = Asu + (st ^ 1) * A_STAGE;
#pragma unroll
            for (int j = 0; j < 8; ++j) {
                int id = tid + 256 * j, r = id >> 3, c = id & 7;
                cp16(an + SWZ(r * 128 + c * 16), g_Abf + (size_t)r * KD + ko + c * 8);
            }
            cp_commit();
        }
        __syncthreads();

        const uint32_t ab = Asu + st * A_STAGE;
        const uint32_t bb = Bsu + st * B_STAGE;
#pragma unroll
        for (int s = 0; s < 4; ++s) {
            const int kb = s * 32;
            uint32_t a[4][4];
#pragma unroll
            for (int mt = 0; mt < 4; ++mt) {
                int m = wm + mt * 16 + mArow;
                ldsm4(a[mt][0], a[mt][1], a[mt][2], a[mt][3],
                      ab + SWZ(m * 128 + kb + kAoff));
            }
            uint32_t b[8][2];
#pragma unroll
            for (int np = 0; np < 4; ++np) {
                int n = wn + np * 16 + nBrow;
                ldsm4(b[np * 2][0], b[np * 2][1], b[np * 2 + 1][0], b[np * 2 + 1][1],
                      bb + SWZ(n * 128 + kb + kBoff));
            }
#pragma unroll
            for (int mt = 0; mt < 4; ++mt)
#pragma unroll
                for (int nt = 0; nt < 8; ++nt)
                    mma_bf16(acc[mt][nt], a[mt][0], a[mt][1], a[mt][2], a[mt][3],
                             b[nt][0], b[nt][1]);
        }
    }

    // epilogue
    const int gr = lane >> 2;
    const int cB = gN + wn + (lane & 3) * 2;
#pragma unroll
    for (int mt = 0; mt < 4; ++mt) {
#pragma unroll
        for (int nt = 0; nt < 8; ++nt) {
            int rr = wm + mt * 16 + gr;
            int cc = cB + nt * 8;
            *(float2*)&g_score[(size_t)rr * NP + cc] =
                make_float2(acc[mt][nt][0], acc[mt][nt][1]);
            *(float2*)&g_score[(size_t)(rr + 8) * NP + cc] =
                make_float2(acc[mt][nt][2], acc[mt][nt][3]);
        }
    }
}

// ---------------------------------------------------------------------------
// Kernel 2: per-row exact radix-select top-K + log-softmax loss + fused mean.
// R5 base; load/transform pass fused with the pass-3 histogram.
// ---------------------------------------------------------------------------
__global__ void topk_loss_kernel(const int* __restrict__ targets,
                                 const int* __restrict__ apl,
                                 const int* __restrict__ plt,
                                 float* __restrict__ out) {
    extern __shared__ uint32_t skey[];   // 16384 keys
    __shared__ uint32_t hist[256];
    __shared__ uint32_t sfx[256];
    __shared__ float    redf[256];
    __shared__ int      redi[256];
    __shared__ uint32_t s_prefix;
    __shared__ int      s_want;
    __shared__ float    posVal[PPOS];
    __shared__ int      nd_s;
    __shared__ uint32_t s_maxkey;
    __shared__ float    s_m;
    __shared__ float    s_f4x;
    __shared__ int      s_exIdx;

    const int r = blockIdx.x;
    const int tid = threadIdx.x;
    const float4* row4 = (const float4*)(g_score + (size_t)r * NP);

    hist[tid] = 0;
    if (tid == 0) { s_maxkey = 0; s_f4x = 0.0f; }
    __syncthreads();

    // fused: load + transform + pass-3 histogram + max
    uint32_t lmax = 0;
#pragma unroll 4
    for (int j = 0; j < NP / 4 / 256; ++j) {
        int i = tid + 256 * j;
        float4 v = row4[i];
        uint32_t k0 = f2key(v.x * INV_TEMP);
        uint32_t k1 = f2key(v.y * INV_TEMP);
        uint32_t k2 = f2key(v.z * INV_TEMP);
        uint32_t k3 = f2key(v.w * INV_TEMP);
        skey[i * 4 + 0] = k0;
        skey[i * 4 + 1] = k1;
        skey[i * 4 + 2] = k2;
        skey[i * 4 + 3] = k3;
        lmax = max(max(max(k0, k1), max(k2, k3)), lmax);
        atomicAdd(&hist[k0 >> 24], 1u);
        atomicAdd(&hist[k1 >> 24], 1u);
        atomicAdd(&hist[k2 >> 24], 1u);
        atomicAdd(&hist[k3 >> 24], 1u);
    }
    atomicMax(&s_maxkey, lmax);
    __syncthreads();

    // positives: dedup, record values, remove from background (skey + hist)
    if (tid == 0) {
        int t = targets[r];
        int y = apl[t];
        int nd = 0;
        int pidx[PPOS];
        uint32_t pkey[PPOS];
        for (int j = 0; j < PPOS; ++j) {
            int p = plt[y * PPOS + j];
            bool dup = false;
            for (int q = 0; q < nd; ++q)
                if (pidx[q] == p) dup = true;
            if (!dup) {
                pidx[nd] = p;
                pkey[nd] = skey[p];
                posVal[nd] = key2f(pkey[nd]);
                ++nd;
            }
        }
        for (int q = 0; q < nd; ++q) {
            hist[pkey[q] >> 24] -= 1u;   // exclude from pass-3 histogram
            skey[pidx[q]] = 0u;          // exclude from later passes
        }
        nd_s = nd;
    }
    __syncthreads();
    const int nd  = nd_s;
    const int nbg = KSEL - nd;

    // radix passes (pass 3 histogram already built)
    uint32_t prefix = 0;
    int want = nbg;
#pragma unroll
    for (int p = 3; p >= 0; --p) {
        if (p < 3) {
            hist[tid] = 0;
            __syncthreads();
#pragma unroll 8
            for (int j = 0; j < NP / 256; ++j) {
                uint32_t u = skey[tid + 256 * j];
                if ((u >> ((p + 1) * 8)) == prefix)
                    atomicAdd(&hist[(u >> (p * 8)) & 0xFFu], 1u);
            }
            __syncthreads();
        }

        uint32_t h = hist[tid];
        sfx[tid] = h;
        __syncthreads();
#pragma unroll
        for (int o = 1; o < 256; o <<= 1) {
            uint32_t v = sfx[tid];
            if (tid + o < 256) v += sfx[tid + o];
            __syncthreads();
            sfx[tid] = v;
            __syncthreads();
        }
        uint32_t excl = sfx[tid] - h;
        if ((int)excl < want && (int)(excl + h) >= want) {
            s_prefix = (prefix << 8) | (uint32_t)tid;
            s_want = want - (int)excl;
        }
        __syncthreads();
        prefix = s_prefix;
        want = s_want;
        __syncthreads();
    }
    const uint32_t T = prefix;
    const int wantEq = want;

    if (tid == 0) {
        float m = key2f(s_maxkey);
        for (int q = 0; q < nd; ++q) m = fmaxf(m, posVal[q]);
        s_m = m;
    }
    __syncthreads();
    const float m = s_m;

    float se = 0.0f;
#pragma unroll 8
    for (int j = 0; j < NP / 256; ++j) {
        uint32_t u = skey[tid + 256 * j];
        if (u > T) se += expf(key2f(u) - m);
    }
    redf[tid] = se;
    __syncthreads();
#pragma unroll
    for (int o = 128; o > 0; o >>= 1) {
        if (tid < o) redf[tid] += redf[tid + o];
        __syncthreads();
    }

    // rare: nd < 4 -> top (4-nd) background values complete the first-P sum
    for (int e = 0; e < PPOS - nd; ++e) {
        uint32_t bk = 0; int bi = -1;
#pragma unroll 8
        for (int j = 0; j < NP / 256; ++j) {
            int i = tid + 256 * j;
            uint32_t u = skey[i];
            if (u > bk) { bk = u; bi = i; }
        }
        sfx[tid] = bk; redi[tid] = bi;
        __syncthreads();
#pragma unroll
        for (int o = 128; o > 0; o >>= 1) {
            if (tid < o && sfx[tid + o] > sfx[tid]) {
                sfx[tid] = sfx[tid + o]; redi[tid] = redi[tid + o];
            }
            __syncthreads();
        }
        if (tid == 0) { s_f4x += key2f(sfx[0]); s_exIdx = redi[0]; }
        __syncthreads();
        if ((s_exIdx & 255) == tid) skey[s_exIdx] = 0u;
        __syncthreads();
    }

    if (tid == 0) {
        float seTot = redf[0] + (float)wantEq * expf(key2f(T) - m);
        float f4 = s_f4x;
        for (int q = 0; q < nd; ++q) {
            seTot += expf(posVal[q] - m);
            f4 += posVal[q];
        }
        float lse = m + logf(seTot);
        atomicAdd(out, (lse - 0.25f * f4) * (1.0f / MB));
    }
}

// ---------------------------------------------------------------------------
extern "C" void kernel_launch(void* const* d_in, const int* in_sizes, int n_in,
                              void* d_out, int out_size) {
    const float* features = (const float*)d_in[0];
    const float* em       = (const float*)d_in[1];
    const int*   targets  = (const int*)d_in[2];
    const int*   apl      = (const int*)d_in[3];
    const int*   plt      = (const int*)d_in[4];
    float* out = (float*)d_out;

    const int gemm_smem = 2 * (A_STAGE + B_STAGE);   // 98304
    cudaFuncSetAttribute(gemm_bf16_kernel,
                         cudaFuncAttributeMaxDynamicSharedMemorySize, gemm_smem);
    const int topk_smem = NP * sizeof(uint32_t);     // 65536
    cudaFuncSetAttribute(topk_loss_kernel,
                         cudaFuncAttributeMaxDynamicSharedMemorySize, topk_smem);

    convertA_kernel<<<128, 256>>>(features, out);
    gemm_bf16_kernel<<<NP / BN, NTHR, gemm_smem>>>(em);
    topk_loss_kernel<<<MB, 256, topk_smem>>>(targets, apl, plt, out);
}